// round 8
// baseline (speedup 1.0000x reference)
#include <cuda_runtime.h>
#include <cuda_fp16.h>

#define D 4096
#define NSTEPS 50
#define NCTA 147
#define ROWS_PER_CTA 28
#define CACHED_ROWS 12           // rows per CTA held in SMEM (192 KB)
#define NTHREADS 896             // 28 warps == exactly the active work units

// Interleaved fp16 matrices: g_AB[r*2D + 2j] = A[r][j], [.. + 1] = B[r][j].
__device__ __align__(16) __half g_AB[(size_t)2 * D * D];
__device__ unsigned int g_bar;      // arrival counter (monotonic per launch)
__device__ unsigned int g_release;  // step release word (single writer per step)

// ---------------------------------------------------------------------------
// prep: interleave A,B into fp16 pairs; reset barrier words.
// ---------------------------------------------------------------------------
__global__ void __launch_bounds__(256) prep_kernel(const float* __restrict__ A,
                                                   const float* __restrict__ B) {
    if (blockIdx.x == 0 && threadIdx.x == 0) { g_bar = 0; g_release = 0; }
    size_t i = (size_t)blockIdx.x * blockDim.x + threadIdx.x;  // float4 index
    float4 a = ((const float4*)A)[i];
    float4 b = ((const float4*)B)[i];
    uint4 o;
    __half2 p;
    p = __floats2half2_rn(a.x, b.x); o.x = *(unsigned int*)&p;
    p = __floats2half2_rn(a.y, b.y); o.y = *(unsigned int*)&p;
    p = __floats2half2_rn(a.z, b.z); o.z = *(unsigned int*)&p;
    p = __floats2half2_rn(a.w, b.w); o.w = *(unsigned int*)&p;
    ((uint4*)g_AB)[i] = o;
}

// acc += A[j]*t + B[j]*d for 4 interleaved (a,b) fp16 pairs in m
__device__ __forceinline__ float dotAB(uint4 m, float4 t, float4 d, float acc) {
    float2 f;
    f = __half22float2(*(__half2*)&m.x); acc = fmaf(f.x, t.x, acc); acc = fmaf(f.y, d.x, acc);
    f = __half22float2(*(__half2*)&m.y); acc = fmaf(f.x, t.y, acc); acc = fmaf(f.y, d.y, acc);
    f = __half22float2(*(__half2*)&m.z); acc = fmaf(f.x, t.z, acc); acc = fmaf(f.y, d.z, acc);
    f = __half22float2(*(__half2*)&m.w); acc = fmaf(f.x, t.w, acc); acc = fmaf(f.y, d.w, acc);
    return acc;
}

// ---------------------------------------------------------------------------
// Persistent recurrence kernel: 147 CTAs x 896 threads (28 warps, all active).
// Warp (rg, ks): 4-row group x 1024-elem K-segment.  Rows 0..11 cached in
// SMEM; rows 12..27 stream from L2 with a register double-buffer (prefetch
// distance 1 iter inside the loop, plus cross-step prefetch issued before the
// barrier spin so iter-0 data lands under barrier latency).
// Barrier: atomicAdd arrivals + separate single-writer release word.
// ---------------------------------------------------------------------------
__global__ void __launch_bounds__(NTHREADS, 1) rnn_kernel(const float* __restrict__ init,
                                                          float* __restrict__ out) {
    extern __shared__ char smem[];
    float4* s_t    = (float4*)smem;                    // theta_t   (16 KB)
    float4* s_d    = (float4*)(smem + 16384);          // delta     (16 KB)
    float*  s_part = (float*)(smem + 32768);           // partials  (512 B)
    uint4*  s_mat  = (uint4*)(smem + 33280);           // cached rows (192 KB)

    const int tid  = threadIdx.x;
    const int warp = tid >> 5;                         // 0..27
    const int lane = tid & 31;
    const int rg   = warp >> 2;                        // 0..6
    const int ks   = warp & 3;                         // 0..3
    const int row_base = blockIdx.x * ROWS_PER_CTA;
    const int row0 = row_base + rg * 4;
    const bool cached = (rg < CACHED_ROWS / 4);        // rg 0..2 -> SMEM rows
    const int seg = ks * 256;                          // float4 offset of segment

    // Preload cached rows into SMEM (once).  Clamp OOB rows of the last CTA.
#pragma unroll
    for (int it = 0; it < CACHED_ROWS; ++it) {
        int sr = min(row_base + it, D - 1);
        for (int i = tid; i < 1024; i += NTHREADS)
            s_mat[it * 1024 + i] = ((const uint4*)g_AB)[(size_t)sr * 1024 + i];
    }

    // Streamed-row pointers (rg >= 3), clamped for the partially-OOB last CTA
    const uint4* r0 = (const uint4*)g_AB + (size_t)min(row0 + 0, D - 1) * 1024;
    const uint4* r1 = (const uint4*)g_AB + (size_t)min(row0 + 1, D - 1) * 1024;
    const uint4* r2 = (const uint4*)g_AB + (size_t)min(row0 + 2, D - 1) * 1024;
    const uint4* r3 = (const uint4*)g_AB + (size_t)min(row0 + 3, D - 1) * 1024;
    // Cached-row pointers (rg < 3)
    const uint4* c0 = s_mat + (size_t)(rg * 4 + 0) * 1024;
    const uint4* c1 = s_mat + (size_t)(rg * 4 + 1) * 1024;
    const uint4* c2 = s_mat + (size_t)(rg * 4 + 2) * 1024;
    const uint4* c3 = s_mat + (size_t)(rg * 4 + 3) * 1024;

    // Prologue: s_t holds theta_{-1} = init_seq[0]
    for (int i = tid; i < 1024; i += NTHREADS)
        s_t[i] = ((const float4*)init)[i];

    // Cross-step prefetch of iter-0 matrix data (streamed warps)
    uint4 n0, n1, n2, n3;
    if (!cached) {
        n0 = r0[seg + lane]; n1 = r1[seg + lane];
        n2 = r2[seg + lane]; n3 = r3[seg + lane];
    }
    __syncthreads();

    for (int t = 0; t < NSTEPS; ++t) {
        // Stage theta_t; delta = theta_t - theta_{t-1} (prev step's s_t)
        const float* th1 = (t == 0) ? init + D : out + (size_t)(t - 1) * D;
        for (int i = tid; i < 1024; i += NTHREADS) {
            float4 nt = __ldcg((const float4*)th1 + i);
            float4 pt = s_t[i];
            s_t[i] = nt;
            s_d[i] = make_float4(nt.x - pt.x, nt.y - pt.y, nt.z - pt.z, nt.w - pt.w);
        }
        __syncthreads();

        float a0 = 0.f, a1 = 0.f, a2 = 0.f, a3 = 0.f;
        if (cached) {
#pragma unroll 2
            for (int i = 0; i < 8; ++i) {
                int idx = seg + i * 32 + lane;
                float4 t4 = s_t[idx];
                float4 d4 = s_d[idx];
                a0 = dotAB(c0[idx], t4, d4, a0);
                a1 = dotAB(c1[idx], t4, d4, a1);
                a2 = dotAB(c2[idx], t4, d4, a2);
                a3 = dotAB(c3[idx], t4, d4, a3);
            }
        } else {
#pragma unroll
            for (int i = 0; i < 8; ++i) {
                int idx = seg + i * 32 + lane;
                uint4 m0 = n0, m1 = n1, m2 = n2, m3 = n3;
                if (i < 7) {                       // prefetch next iter
                    int nx = idx + 32;
                    n0 = r0[nx]; n1 = r1[nx]; n2 = r2[nx]; n3 = r3[nx];
                }
                float4 t4 = s_t[idx];
                float4 d4 = s_d[idx];
                a0 = dotAB(m0, t4, d4, a0);
                a1 = dotAB(m1, t4, d4, a1);
                a2 = dotAB(m2, t4, d4, a2);
                a3 = dotAB(m3, t4, d4, a3);
            }
        }

#pragma unroll
        for (int off = 16; off; off >>= 1) {
            a0 += __shfl_xor_sync(0xffffffffu, a0, off);
            a1 += __shfl_xor_sync(0xffffffffu, a1, off);
            a2 += __shfl_xor_sync(0xffffffffu, a2, off);
            a3 += __shfl_xor_sync(0xffffffffu, a3, off);
        }
        if (lane == 0) {
            s_part[(rg * 4 + 0) * 4 + ks] = a0;
            s_part[(rg * 4 + 1) * 4 + ks] = a1;
            s_part[(rg * 4 + 2) * 4 + ks] = a2;
            s_part[(rg * 4 + 3) * 4 + ks] = a3;
        }
        __syncthreads();                               // sync A: partials ready

        if (warp == 0) {
            // Combine K-segment partials and publish rows (warp 0 only)
            if (tid < ROWS_PER_CTA) {
                int row = row_base + tid;
                if (row < D) {
                    float v = (s_part[tid * 4 + 0] + s_part[tid * 4 + 1]) +
                              (s_part[tid * 4 + 2] + s_part[tid * 4 + 3]);
                    __stcg(out + (size_t)t * D + row, v);
                }
            }
            __syncwarp();
            if (tid == 0) {
                __threadfence();                       // release this CTA's rows
                unsigned int old = atomicAdd(&g_bar, 1u);
                unsigned int target = (unsigned int)(t + 1) * NCTA;
                if (old == target - 1u)
                    *(volatile unsigned int*)&g_release = (unsigned int)(t + 1);
                while (*(volatile unsigned int*)&g_release < (unsigned int)(t + 1)) { }
                __threadfence();                       // acquire
            }
        } else if (!cached && t + 1 < NSTEPS) {
            // Cross-step prefetch: iter-0 matrix loads complete under the barrier
            n0 = r0[seg + lane]; n1 = r1[seg + lane];
            n2 = r2[seg + lane]; n3 = r3[seg + lane];
        }
        __syncthreads();                               // sync B: release everyone
    }
}

// ---------------------------------------------------------------------------
// Launch: prep (convert + barrier reset), then ONE persistent kernel with
// opt-in 224.5 KB dynamic SMEM.
// ---------------------------------------------------------------------------
extern "C" void kernel_launch(void* const* d_in, const int* in_sizes, int n_in,
                              void* d_out, int out_size) {
    const float* init = (const float*)d_in[0];  // [2, D]
    const float* A    = (const float*)d_in[1];  // [D, D]
    const float* B    = (const float*)d_in[2];  // [D, D]
    float* out = (float*)d_out;                 // [NSTEPS, D]

    const int smem_bytes = 33280 + CACHED_ROWS * 1024 * 16;  // 229,888 B
    cudaFuncSetAttribute(rnn_kernel, cudaFuncAttributeMaxDynamicSharedMemorySize,
                         smem_bytes);

    prep_kernel<<<(D * (size_t)D / 4) / 256, 256>>>(A, B);
    rnn_kernel<<<NCTA, NTHREADS, smem_bytes>>>(init, out);
}